// round 2
// baseline (speedup 1.0000x reference)
#include <cuda_runtime.h>

// SphericalMessagePassing: fused flash-attention-style kernel, fp32 SIMT.
// N=8192 nodes, D=256. Grid = 128 CTAs (64 query rows each), 256 threads.
//
// Per CTA:
//   load Q tile (64x256) transposed into smem (swizzled)
//   for each 64-key block:
//     load K tile into smem in BOTH layouts (k-major Kt for S-gemm, n-major Kn for PV)
//     S = Q K^T (register 4x4 tiles), s *= adj, p = exp(s)  [sim in [-1,1] -> no max needed]
//     l += rowsum(p); store P transposed; acc(4x16 per thread) += P @ K
//   message = acc / l  -> smem (transposed, reuse Qt buffer)
//   out = message @ W^T + b  (4 chunks of 64 over k, W tile transposed into Kn buffer)
//   row L2-normalize, store.

#define N_  8192
#define D_  256
#define BM  64
#define BN  64
#define NBLK (N_ / BN)   // 128

// float4-unit swizzle: physical col4 = col4 ^ ((row>>2)&7). Conflict-free for
// both row-contiguous reads and 4x4-block transposed column writes.
__device__ __forceinline__ int swz16(int row, int col4) {
    return row * 16 + (col4 ^ ((row >> 2) & 7));
}
__device__ __forceinline__ int swz64(int row, int col4) {
    return row * 64 + (col4 ^ ((row >> 2) & 7));
}

__global__ __launch_bounds__(256, 1)
void smp_kernel(const float* __restrict__ z, const float* __restrict__ adj,
                const float* __restrict__ W, const float* __restrict__ bias,
                float* __restrict__ out)
{
    // smem (float4 units):
    //   Qt  [256 rows][16 f4]  = 4096 f4   (Q transposed, swizzled; reused for message)
    //   Kt  [256 rows][16 f4]  = 4096 f4   (K transposed, swizzled)
    //   Kn  [ 64 rows][64 f4]  = 4096 f4   (K natural; reused for W tile, swizzled there)
    //   Ps  [ 64 rows][16 f4]  = 1024 f4   (P transposed, swizzled)
    //   lsum[64], nrm[64] floats
    extern __shared__ float4 sm4[];
    float4* Qt = sm4;
    float4* Kt = sm4 + 4096;
    float4* Kn = sm4 + 8192;
    float4* Ps = sm4 + 12288;
    float*  smf  = (float*)(sm4 + 13312);
    float*  lsum = smf;
    float*  nrm  = smf + 64;

    const int tid = threadIdx.x;
    const int tx  = tid & 15;    // n-group / d-group (16)
    const int ty  = tid >> 4;    // m-group (16)
    const int bm  = blockIdx.x;

    const float4* z4 = (const float4*)z;
    const float4* adj4 = (const float4*)adj;
    const float4* W4 = (const float4*)W;
    const float4* b4 = (const float4*)bias;
    float4* out4 = (float4*)out;

    if (tid < 64) { lsum[tid] = 0.0f; nrm[tid] = 0.0f; }

    // ---- load Q tile transposed: Qt[k][m], 4x4 block transpose ----
    #pragma unroll
    for (int c = 0; c < 4; ++c) {
        int g  = tid + 256 * c;      // 1024 4x4 blocks
        int d4 = g & 63;
        int m4 = g >> 6;
        float4 v0 = z4[(size_t)(bm * 64 + 4 * m4 + 0) * 64 + d4];
        float4 v1 = z4[(size_t)(bm * 64 + 4 * m4 + 1) * 64 + d4];
        float4 v2 = z4[(size_t)(bm * 64 + 4 * m4 + 2) * 64 + d4];
        float4 v3 = z4[(size_t)(bm * 64 + 4 * m4 + 3) * 64 + d4];
        int k0 = 4 * d4;
        Qt[swz16(k0 + 0, m4)] = make_float4(v0.x, v1.x, v2.x, v3.x);
        Qt[swz16(k0 + 1, m4)] = make_float4(v0.y, v1.y, v2.y, v3.y);
        Qt[swz16(k0 + 2, m4)] = make_float4(v0.z, v1.z, v2.z, v3.z);
        Qt[swz16(k0 + 3, m4)] = make_float4(v0.w, v1.w, v2.w, v3.w);
    }

    float acc[4][16];
    #pragma unroll
    for (int a = 0; a < 4; ++a)
        #pragma unroll
        for (int b = 0; b < 16; ++b) acc[a][b] = 0.0f;
    float lp[4] = {0.0f, 0.0f, 0.0f, 0.0f};

    for (int kb = 0; kb < NBLK; ++kb) {
        __syncthreads();   // previous-iter PV done (also orders Q-tile stores, 1st iter)
        // ---- load K tile: Kn (natural) + Kt (transposed, swizzled) ----
        #pragma unroll
        for (int c = 0; c < 4; ++c) {
            int g  = tid + 256 * c;
            int d4 = g & 63;
            int n4 = g >> 6;
            float4 v0 = z4[(size_t)(kb * 64 + 4 * n4 + 0) * 64 + d4];
            float4 v1 = z4[(size_t)(kb * 64 + 4 * n4 + 1) * 64 + d4];
            float4 v2 = z4[(size_t)(kb * 64 + 4 * n4 + 2) * 64 + d4];
            float4 v3 = z4[(size_t)(kb * 64 + 4 * n4 + 3) * 64 + d4];
            Kn[(4 * n4 + 0) * 64 + d4] = v0;
            Kn[(4 * n4 + 1) * 64 + d4] = v1;
            Kn[(4 * n4 + 2) * 64 + d4] = v2;
            Kn[(4 * n4 + 3) * 64 + d4] = v3;
            int k0 = 4 * d4;
            Kt[swz16(k0 + 0, n4)] = make_float4(v0.x, v1.x, v2.x, v3.x);
            Kt[swz16(k0 + 1, n4)] = make_float4(v0.y, v1.y, v2.y, v3.y);
            Kt[swz16(k0 + 2, n4)] = make_float4(v0.z, v1.z, v2.z, v3.z);
            Kt[swz16(k0 + 3, n4)] = make_float4(v0.w, v1.w, v2.w, v3.w);
        }
        __syncthreads();

        // ---- S = Q K^T : 4x4 register tile ----
        float s[4][4];
        #pragma unroll
        for (int a = 0; a < 4; ++a)
            #pragma unroll
            for (int b = 0; b < 4; ++b) s[a][b] = 0.0f;

        #pragma unroll 8
        for (int k = 0; k < 256; ++k) {
            float4 qv = Qt[swz16(k, ty)];
            float4 kv = Kt[swz16(k, tx)];
            float qq[4] = {qv.x, qv.y, qv.z, qv.w};
            float kk[4] = {kv.x, kv.y, kv.z, kv.w};
            #pragma unroll
            for (int mi = 0; mi < 4; ++mi)
                #pragma unroll
                for (int ni = 0; ni < 4; ++ni)
                    s[mi][ni] += qq[mi] * kk[ni];
        }

        // ---- multiplicative mask + exp (safe: |s| <= 1) + row-sum partials ----
        float p[4][4];
        #pragma unroll
        for (int mi = 0; mi < 4; ++mi) {
            float4 a = adj4[(size_t)(bm * 64 + 4 * ty + mi) * (N_ / 4) + kb * 16 + tx];
            p[mi][0] = __expf(s[mi][0] * a.x);
            p[mi][1] = __expf(s[mi][1] * a.y);
            p[mi][2] = __expf(s[mi][2] * a.z);
            p[mi][3] = __expf(s[mi][3] * a.w);
            lp[mi] += (p[mi][0] + p[mi][1]) + (p[mi][2] + p[mi][3]);
        }

        // ---- store P transposed: Ps[n][m] ----
        #pragma unroll
        for (int ni = 0; ni < 4; ++ni) {
            int row = 4 * tx + ni;
            Ps[swz16(row, ty)] = make_float4(p[0][ni], p[1][ni], p[2][ni], p[3][ni]);
        }
        __syncthreads();

        // ---- acc += P @ V (V rows = K rows = this z block) ----
        #pragma unroll 2
        for (int n = 0; n < 64; ++n) {
            float4 pv = Ps[swz16(n, ty)];
            float pr[4] = {pv.x, pv.y, pv.z, pv.w};
            float4 w0 = Kn[n * 64 + 0 * 16 + tx];
            float4 w1 = Kn[n * 64 + 1 * 16 + tx];
            float4 w2 = Kn[n * 64 + 2 * 16 + tx];
            float4 w3 = Kn[n * 64 + 3 * 16 + tx];
            float bb[16] = {w0.x, w0.y, w0.z, w0.w, w1.x, w1.y, w1.z, w1.w,
                            w2.x, w2.y, w2.z, w2.w, w3.x, w3.y, w3.z, w3.w};
            #pragma unroll
            for (int mi = 0; mi < 4; ++mi)
                #pragma unroll
                for (int cc = 0; cc < 16; ++cc)
                    acc[mi][cc] += pr[mi] * bb[cc];
        }
    }

    // ---- softmax denominator reduce ----
    __syncthreads();
    #pragma unroll
    for (int mi = 0; mi < 4; ++mi) atomicAdd(&lsum[4 * ty + mi], lp[mi]);
    __syncthreads();
    float inv[4];
    #pragma unroll
    for (int mi = 0; mi < 4; ++mi) inv[mi] = 1.0f / lsum[4 * ty + mi];

    // ---- message (normalized) into smem transposed (reuse Qt): Ms[d][m] ----
    #pragma unroll
    for (int i = 0; i < 4; ++i) {
        #pragma unroll
        for (int j = 0; j < 4; ++j) {
            int row = 64 * i + 4 * tx + j;
            Qt[swz16(row, ty)] = make_float4(acc[0][i * 4 + j] * inv[0],
                                             acc[1][i * 4 + j] * inv[1],
                                             acc[2][i * 4 + j] * inv[2],
                                             acc[3][i * 4 + j] * inv[3]);
        }
    }

    // ---- out = message @ W^T, reuse acc registers ----
    #pragma unroll
    for (int a = 0; a < 4; ++a)
        #pragma unroll
        for (int b = 0; b < 16; ++b) acc[a][b] = 0.0f;

    for (int kc = 0; kc < 4; ++kc) {
        __syncthreads();  // Ms stores visible (kc=0); Ws buffer free (kc>0)
        // load W chunk transposed into Kn buffer: Ws[k][j] = W[j][kc*64+k], swizzled
        #pragma unroll
        for (int c = 0; c < 4; ++c) {
            int g  = tid + 256 * c;
            int k4 = g & 15;
            int j4 = g >> 4;    // 0..63
            float4 v0 = W4[(size_t)(4 * j4 + 0) * 64 + kc * 16 + k4];
            float4 v1 = W4[(size_t)(4 * j4 + 1) * 64 + kc * 16 + k4];
            float4 v2 = W4[(size_t)(4 * j4 + 2) * 64 + kc * 16 + k4];
            float4 v3 = W4[(size_t)(4 * j4 + 3) * 64 + kc * 16 + k4];
            int r0 = 4 * k4;
            Kn[swz64(r0 + 0, j4)] = make_float4(v0.x, v1.x, v2.x, v3.x);
            Kn[swz64(r0 + 1, j4)] = make_float4(v0.y, v1.y, v2.y, v3.y);
            Kn[swz64(r0 + 2, j4)] = make_float4(v0.z, v1.z, v2.z, v3.z);
            Kn[swz64(r0 + 3, j4)] = make_float4(v0.w, v1.w, v2.w, v3.w);
        }
        __syncthreads();

        #pragma unroll 2
        for (int n = 0; n < 64; ++n) {
            float4 mv = Qt[swz16(kc * 64 + n, ty)];
            float pr[4] = {mv.x, mv.y, mv.z, mv.w};
            float4 w0 = Kn[swz64(n, 0 * 16 + tx)];
            float4 w1 = Kn[swz64(n, 1 * 16 + tx)];
            float4 w2 = Kn[swz64(n, 2 * 16 + tx)];
            float4 w3 = Kn[swz64(n, 3 * 16 + tx)];
            float bb[16] = {w0.x, w0.y, w0.z, w0.w, w1.x, w1.y, w1.z, w1.w,
                            w2.x, w2.y, w2.z, w2.w, w3.x, w3.y, w3.z, w3.w};
            #pragma unroll
            for (int mi = 0; mi < 4; ++mi)
                #pragma unroll
                for (int cc = 0; cc < 16; ++cc)
                    acc[mi][cc] += pr[mi] * bb[cc];
        }
    }

    // ---- + bias, row L2 norm ----
    float ss[4] = {0.0f, 0.0f, 0.0f, 0.0f};
    #pragma unroll
    for (int i = 0; i < 4; ++i) {
        float4 bv = b4[i * 16 + tx];
        float bj[4] = {bv.x, bv.y, bv.z, bv.w};
        #pragma unroll
        for (int mi = 0; mi < 4; ++mi) {
            #pragma unroll
            for (int j = 0; j < 4; ++j) {
                acc[mi][i * 4 + j] += bj[j];
                ss[mi] += acc[mi][i * 4 + j] * acc[mi][i * 4 + j];
            }
        }
    }
    __syncthreads();   // order against lsum reads before nrm atomics
    #pragma unroll
    for (int mi = 0; mi < 4; ++mi) atomicAdd(&nrm[4 * ty + mi], ss[mi]);
    __syncthreads();

    #pragma unroll
    for (int mi = 0; mi < 4; ++mi) {
        float scale = 1.0f / fmaxf(sqrtf(nrm[4 * ty + mi]), 1e-12f);
        int grow = bm * 64 + 4 * ty + mi;
        #pragma unroll
        for (int i = 0; i < 4; ++i) {
            out4[(size_t)grow * 64 + i * 16 + tx] =
                make_float4(acc[mi][i * 4 + 0] * scale, acc[mi][i * 4 + 1] * scale,
                            acc[mi][i * 4 + 2] * scale, acc[mi][i * 4 + 3] * scale);
        }
    }
}

extern "C" void kernel_launch(void* const* d_in, const int* in_sizes, int n_in,
                              void* d_out, int out_size)
{
    const float* z    = (const float*)d_in[0];
    const float* adj  = (const float*)d_in[1];
    const float* W    = (const float*)d_in[2];
    const float* bias = (const float*)d_in[3];
    float* out = (float*)d_out;

    static bool attr_set = false;
    const int smem_bytes = 13312 * 16 + 512;   // 213504 B
    if (!attr_set) {
        cudaFuncSetAttribute(smp_kernel, cudaFuncAttributeMaxDynamicSharedMemorySize, smem_bytes);
        attr_set = true;
    }
    smp_kernel<<<N_ / BM, 256, smem_bytes>>>(z, adj, W, bias, out);
}